// round 14
// baseline (speedup 1.0000x reference)
#include <cuda_runtime.h>

#define TPB 160
#define NS  160   // samples per block, 1 per thread, 2 CTAs/SM (10 warps)

typedef unsigned long long u64;

// ---- shared memory layout (float indices), per-CTA 114,224 B ----
#define OFF_W1W 0        // W1 window [k=32][68] (quarter of K)
#define OFF_W2T 2176     // [k=64][32]
#define OFF_W3T 4224     // [32][4]
#define OFF_V1T 4352     // [3][32]
#define OFF_V2T 4448     // [k=32][64]
#define OFF_V3W 6496     // V3 window [j=16][64] (1/8 of J)
#define OFF_B1  7520
#define OFF_B2  7584
#define OFF_B3  7616
#define OFF_C1  7620
#define OFF_C2  7652
#define OFF_C3  7716
#define OFF_EW  7844     // 66 used
#define OFF_EB  7912
#define OFF_AB  7916     // buffer: 160 rows x 129 floats
#define SMEM_FLOATS (OFF_AB + NS*129)

__device__ __forceinline__ float sigmoidf(float v) {
    return __fdividef(1.0f, 1.0f + __expf(-v));
}
__device__ __forceinline__ void ffma2(u64& acc, u64 w, u64 v) {
    asm("fma.rn.f32x2 %0, %1, %2, %0;" : "+l"(acc) : "l"(w), "l"(v));
}
__device__ __forceinline__ u64 pack2(float v) {
    u64 r; asm("mov.b64 %0, {%1, %1};" : "=l"(r) : "f"(v)); return r;
}
__device__ __forceinline__ u64 pack2f(float a, float b) {
    u64 r; asm("mov.b64 %0, {%1, %2};" : "=l"(r) : "f"(a), "f"(b)); return r;
}
__device__ __forceinline__ void unpack2(u64 p, float& a, float& b) {
    asm("mov.b64 {%0, %1}, %2;" : "=f"(a), "=f"(b) : "l"(p));
}

// one k-step of a dual (value+tangent) GEMM, NOUT outputs, weights from smem
template<int NOUT>
__device__ __forceinline__ void dual_step(const float* wrow, float hv_s, float tv_s,
                                          u64* aV, u64* aT) {
    u64 hv = pack2(hv_s), tv = pack2(tv_s);
    const ulonglong2* wp = (const ulonglong2*)wrow;
    #pragma unroll
    for (int q = 0; q < NOUT / 4; q++) {
        ulonglong2 wq = wp[q];
        ffma2(aV[2*q],   wq.x, hv);
        ffma2(aV[2*q+1], wq.y, hv);
        ffma2(aT[2*q],   wq.x, tv);
        ffma2(aT[2*q+1], wq.y, tv);
    }
}

template<int NOUT>
__device__ __forceinline__ void init_dual(u64* aV, u64* aT, const float* bias) {
    const u64* bp = (const u64*)bias;
    #pragma unroll
    for (int p = 0; p < NOUT/2; p++) { aV[p] = bp[p]; aT[p] = 0ull; }
}

// sigmoid boundary: value -> row[j], tangent -> row[64+j]
template<int NOUT>
__device__ __forceinline__ void boundary_row(const u64* aV, const u64* aT, float* row) {
    #pragma unroll
    for (int p = 0; p < NOUT/2; p++) {
        float a, b, ta, tb;
        unpack2(aV[p], a, b); unpack2(aT[p], ta, tb);
        float s0 = sigmoidf(a), s1 = sigmoidf(b);
        row[2*p]      = s0;
        row[2*p+1]    = s1;
        row[64+2*p]   = s0 * (1.f - s0) * ta;
        row[64+2*p+1] = s1 * (1.f - s1) * tb;
    }
}

__global__ __launch_bounds__(TPB, 2)
void sindy_fused_kernel(
    const float* __restrict__ x,  const float* __restrict__ dx,
    const float* __restrict__ W1, const float* __restrict__ b1,
    const float* __restrict__ W2, const float* __restrict__ b2,
    const float* __restrict__ W3, const float* __restrict__ b3,
    const float* __restrict__ V1, const float* __restrict__ c1,
    const float* __restrict__ V2, const float* __restrict__ c2,
    const float* __restrict__ V3, const float* __restrict__ c3,
    const float* __restrict__ Ew, const float* __restrict__ Eb,
    float* __restrict__ out, int n)
{
    extern __shared__ float sm[];
    const int tid = threadIdx.x;
    const long long base = (long long)blockIdx.x * NS;

    // stage one 32-k quarter of W1 (transposed) into the window, stride 68
    auto stage_w1 = [&](int q) {
        for (int i = tid; i < 32*64; i += TPB) {
            int j = i >> 5, kl = i & 31;
            sm[OFF_W1W + kl*68 + j] = W1[j*128 + q*32 + kl];
        }
    };
    // stage one 16-j window of V3 (natural j-major), stride 64
    auto stage_v3 = [&](int w) {
        for (int i = tid; i < 16*64; i += TPB) {
            int jl = i >> 6, k = i & 63;
            sm[OFF_V3W + jl*64 + k] = V3[(w*16 + jl)*64 + k];
        }
    };

    // ---- stage resident weights ----
    stage_w1(0);
    for (int i = tid; i < 32*64;  i += TPB) { int j = i >> 6, k = i & 63;  sm[OFF_W2T + k*32 + j] = W2[i]; }
    for (int i = tid; i < 3*32;   i += TPB) { int j = i >> 5, k = i & 31;  sm[OFF_W3T + k*4  + j] = W3[i]; }
    for (int i = tid; i < 32*3;   i += TPB) { int j = i / 3,  k = i % 3;   sm[OFF_V1T + k*32 + j] = V1[i]; }
    for (int i = tid; i < 64*32;  i += TPB) { int j = i >> 5, k = i & 31;  sm[OFF_V2T + k*64 + j] = V2[i]; }
    if (tid < 64)  sm[OFF_B1 + tid] = b1[tid];
    if (tid < 32)  sm[OFF_B2 + tid] = b2[tid];
    if (tid < 4)   sm[OFF_B3 + tid] = (tid < 3) ? b3[tid] : 0.f;
    if (tid < 32)  sm[OFF_C1 + tid] = c1[tid];
    if (tid < 64)  sm[OFF_C2 + tid] = c2[tid];
    if (tid < 128) sm[OFF_C3 + tid] = c3[tid];
    if (tid < 66)  sm[OFF_EW + tid] = Ew[tid];
    if (tid < 3)   sm[OFF_EB + tid] = Eb[tid];

    float* Abuf = sm + OFF_AB;

    long long rem = (long long)n - base;
    const int nv = (rem >= NS) ? NS : (int)rem;
    const bool active = tid < nv;
    float* row = Abuf + tid * 129;

    // stage one 64-column wave of x into row[0:64] and dx into row[64:128]
    auto stage_wave = [&](int w) {
        if (nv == NS) {
            const float4* x4  = (const float4*)x;
            const float4* dx4 = (const float4*)dx;
            for (int i = tid; i < NS * 16; i += TPB) {
                int r = i >> 4, q = i & 15;
                size_t gi = (size_t)(base + r) * 32 + (size_t)w * 16 + q;
                float4 v = x4[gi];
                float* d = &Abuf[r*129 + q*4];
                d[0] = v.x; d[1] = v.y; d[2] = v.z; d[3] = v.w;
                v = dx4[gi];
                d = &Abuf[r*129 + 64 + q*4];
                d[0] = v.x; d[1] = v.y; d[2] = v.z; d[3] = v.w;
            }
        } else {
            for (int i = tid; i < nv * 64; i += TPB) {
                int r = i >> 6, c = i & 63;
                size_t gi = (size_t)(base + r) * 128 + (size_t)w * 64 + c;
                Abuf[r*129 + c]      = x[gi];
                Abuf[r*129 + 64 + c] = dx[gi];
            }
        }
    };

    const size_t n3  = (size_t)n * 3;
    const size_t xbo = (size_t)n * 9;
    const size_t dxo = xbo + (size_t)n * 128;

    // ================= encoder L1: 128 -> 64 (4 k-chunks, windowed W1) =================
    u64 aV[32], aT[32];
    stage_wave(0);
    __syncthreads();
    if (active) {
        init_dual<64>(aV, aT, &sm[OFF_B1]);
        #pragma unroll 4
        for (int k = 0; k < 32; k++)
            dual_step<64>(&sm[OFF_W1W + k*68], row[k], row[64+k], aV, aT);
    }
    __syncthreads();
    stage_w1(1);
    __syncthreads();
    if (active) {
        #pragma unroll 4
        for (int k = 0; k < 32; k++)
            dual_step<64>(&sm[OFF_W1W + k*68], row[32+k], row[96+k], aV, aT);
    }
    __syncthreads();
    stage_wave(1);
    stage_w1(2);
    __syncthreads();
    if (active) {
        #pragma unroll 4
        for (int k = 0; k < 32; k++)
            dual_step<64>(&sm[OFF_W1W + k*68], row[k], row[64+k], aV, aT);
    }
    __syncthreads();
    stage_w1(3);
    __syncthreads();

    u64 hp[32], tp[32];   // packed h2d/t2d for decoder L3 (filled later)

    if (active) {
        #pragma unroll 4
        for (int k = 0; k < 32; k++)
            dual_step<64>(&sm[OFF_W1W + k*68], row[32+k], row[96+k], aV, aT);
        boundary_row<64>(aV, aT, row);   // h1 -> row[0:64], t1 -> row[64:128]

        // ================= encoder L2: 64 -> 32 =================
        u64 bV[16], bT[16];
        init_dual<32>(bV, bT, &sm[OFF_B2]);
        #pragma unroll 4
        for (int k = 0; k < 64; k++)
            dual_step<32>(&sm[OFF_W2T + k*32], row[k], row[64+k], bV, bT);
        boundary_row<32>(bV, bT, row);   // h2 -> row[0:32], t2 -> row[64:96]

        // ================= encoder L3: 32 -> 3 =================
        float z0 = sm[OFF_B3+0], z1 = sm[OFF_B3+1], z2 = sm[OFF_B3+2];
        float tz0 = 0.f, tz1 = 0.f, tz2 = 0.f;
        #pragma unroll
        for (int k = 0; k < 32; k++) {
            float v = row[k], t = row[64+k];
            float w0 = sm[OFF_W3T + k*4 + 0];
            float w1 = sm[OFF_W3T + k*4 + 1];
            float w2 = sm[OFF_W3T + k*4 + 2];
            z0 += w0*v; tz0 += w0*t;
            z1 += w1*v; tz1 += w1*t;
            z2 += w2*v; tz2 += w2*t;
        }
        size_t sI = (size_t)(base + tid);
        out[     sI*3+0] = z0;  out[     sI*3+1] = z1;  out[     sI*3+2] = z2;   // z
        out[n3 + sI*3+0] = tz0; out[n3 + sI*3+1] = tz1; out[n3 + sI*3+2] = tz2;  // dz

        // ================= SINDy library + dzb =================
        float th[22];
        th[0]=1.f; th[1]=1.f; th[2]=1.f;
        th[3]=z0; th[4]=z1; th[5]=z2;
        th[6]=z0*z0; th[7]=z0*z1; th[8]=z0*z2;
        th[9]=z1*z1; th[10]=z1*z2; th[11]=z2*z2;
        th[12]=th[6]*z0; th[13]=th[6]*z1; th[14]=th[6]*z2;
        th[15]=th[7]*z1; th[16]=th[7]*z2; th[17]=th[8]*z2;
        th[18]=th[9]*z1; th[19]=th[9]*z2; th[20]=th[10]*z2;
        th[21]=th[11]*z2;
        float q0 = sm[OFF_EB+0], q1 = sm[OFF_EB+1], q2 = sm[OFF_EB+2];
        #pragma unroll
        for (int k = 0; k < 22; k++) {
            q0 += sm[OFF_EW +      k] * th[k];
            q1 += sm[OFF_EW + 22 + k] * th[k];
            q2 += sm[OFF_EW + 44 + k] * th[k];
        }
        out[2*n3 + sI*3+0] = q0; out[2*n3 + sI*3+1] = q1; out[2*n3 + sI*3+2] = q2; // dzb

        // ================= decoder L1: 3 -> 32 =================
        u64 dV[16], dT[16];
        init_dual<32>(dV, dT, &sm[OFF_C1]);
        dual_step<32>(&sm[OFF_V1T + 0*32], z0, q0, dV, dT);
        dual_step<32>(&sm[OFF_V1T + 1*32], z1, q1, dV, dT);
        dual_step<32>(&sm[OFF_V1T + 2*32], z2, q2, dV, dT);
        boundary_row<32>(dV, dT, row);   // h1d -> row[0:32], t1d -> row[64:96]

        // ================= decoder L2: 32 -> 64 =================
        u64 eV[32], eT[32];
        init_dual<64>(eV, eT, &sm[OFF_C2]);
        #pragma unroll 4
        for (int k = 0; k < 32; k++)
            dual_step<64>(&sm[OFF_V2T + k*64], row[k], row[64+k], eV, eT);
        // boundary -> packed registers (h2d/t2d pairs for L3)
        #pragma unroll
        for (int p = 0; p < 32; p++) {
            float a, b, ta, tb;
            unpack2(eV[p], a, b); unpack2(eT[p], ta, tb);
            float s0 = sigmoidf(a), s1 = sigmoidf(b);
            hp[p] = pack2f(s0, s1);
            tp[p] = pack2f(s0 * (1.f - s0) * ta, s1 * (1.f - s1) * tb);
        }
    }

    // ================= decoder L3: 64 -> 128, 8 windows of 16 j =================
    const bool fast = (nv == NS) && ((n & 3) == 0);

    auto dec3_compute = [&](int W) {
        if (active) {
            #pragma unroll 2
            for (int j = 0; j < 16; j++) {
                int jj = W*16 + j;
                int rc = jj & 63;          // slot within row half-buffer
                u64 aV0 = pack2f(sm[OFF_C3 + jj], 0.f);
                u64 aV1 = 0ull, aT0 = 0ull, aT1 = 0ull;
                const ulonglong2* wp = (const ulonglong2*)&sm[OFF_V3W + j*64];
                #pragma unroll
                for (int q = 0; q < 16; q += 2) {
                    ulonglong2 w0 = wp[q], w1 = wp[q+1];
                    ffma2(aV0, w0.x, hp[2*q]);   ffma2(aV0, w0.y, hp[2*q+1]);
                    ffma2(aT0, w0.x, tp[2*q]);   ffma2(aT0, w0.y, tp[2*q+1]);
                    ffma2(aV1, w1.x, hp[2*q+2]); ffma2(aV1, w1.y, hp[2*q+3]);
                    ffma2(aT1, w1.x, tp[2*q+2]); ffma2(aT1, w1.y, tp[2*q+3]);
                }
                float v0,v1,v2,v3,t0,t1,t2,t3;
                unpack2(aV0, v0, v1); unpack2(aV1, v2, v3);
                unpack2(aT0, t0, t1); unpack2(aT1, t2, t3);
                row[rc]      = (v0+v1) + (v2+v3);   // xb col jj
                row[64 + rc] = (t0+t1) + (t2+t3);   // dxb col jj
            }
        }
    };
    auto writeback = [&](int H) {
        if (fast) {
            float4* ox = (float4*)(out + xbo);
            float4* od = (float4*)(out + dxo);
            for (int i = tid; i < NS * 16; i += TPB) {
                int r = i >> 4, q = i & 15;
                size_t gi = (size_t)(base + r) * 32 + (size_t)H * 16 + q;
                const float* ap = &Abuf[r*129 + q*4];
                float4 v; v.x = ap[0]; v.y = ap[1]; v.z = ap[2]; v.w = ap[3];
                ox[gi] = v;
                const float* bp = &Abuf[r*129 + 64 + q*4];
                v.x = bp[0]; v.y = bp[1]; v.z = bp[2]; v.w = bp[3];
                od[gi] = v;
            }
        } else {
            for (int i = tid; i < nv * 64; i += TPB) {
                int r = i >> 6, c = i & 63;
                size_t gi = (size_t)(base + r) * 128 + (size_t)H * 64 + c;
                out[xbo + gi] = Abuf[r*129 + c];
                out[dxo + gi] = Abuf[r*129 + 64 + c];
            }
        }
    };

    #pragma unroll 1
    for (int W = 0; W < 8; W++) {
        stage_v3(W);
        __syncthreads();          // window staged
        dec3_compute(W);
        __syncthreads();          // computes done before restage / writeback
        if (W == 3) {
            writeback(0);         // cols 0..63 complete
            __syncthreads();      // writeback done before rows overwritten
        }
    }
    writeback(1);                 // cols 64..127 (post final sync above)
}

extern "C" void kernel_launch(void* const* d_in, const int* in_sizes, int n_in,
                              void* d_out, int out_size) {
    (void)n_in; (void)out_size;
    const float* x  = (const float*)d_in[0];
    const float* dx = (const float*)d_in[1];
    const float* W1 = (const float*)d_in[2];
    const float* b1 = (const float*)d_in[3];
    const float* W2 = (const float*)d_in[4];
    const float* b2 = (const float*)d_in[5];
    const float* W3 = (const float*)d_in[6];
    const float* b3 = (const float*)d_in[7];
    const float* V1 = (const float*)d_in[8];
    const float* c1 = (const float*)d_in[9];
    const float* V2 = (const float*)d_in[10];
    const float* c2 = (const float*)d_in[11];
    const float* V3 = (const float*)d_in[12];
    const float* c3 = (const float*)d_in[13];
    const float* Ew = (const float*)d_in[14];
    const float* Eb = (const float*)d_in[15];
    float* out = (float*)d_out;

    const int n = in_sizes[0] / 128;
    const size_t smem = SMEM_FLOATS * sizeof(float);
    cudaFuncSetAttribute(sindy_fused_kernel,
                         cudaFuncAttributeMaxDynamicSharedMemorySize, (int)smem);
    const int grid = (n + NS - 1) / NS;
    sindy_fused_kernel<<<grid, TPB, smem>>>(x, dx, W1, b1, W2, b2, W3, b3,
                                            V1, c1, V2, c2, V3, c3, Ew, Eb,
                                            out, n);
}

// round 17
// speedup vs baseline: 1.6625x; 1.6625x over previous
#include <cuda_runtime.h>

#define TPB 128
#define NS  128   // samples per block, 1 per thread, 2 CTAs/SM

typedef unsigned long long u64;

// ---- shared memory layout (float indices), per-CTA 110,000 B ----
#define OFF_W1W 0        // W1 window [k=32][68] (quarter of K)
#define OFF_W2T 2176     // [k=64][32]
#define OFF_W3T 4224     // [32][4]
#define OFF_V1T 4352     // [3][32]
#define OFF_V2T 4448     // [k=32][64]
#define OFF_V3W 6496     // V3 window [j=16][64] (1/8 of J) -- rest spare
#define OFF_B1  10592
#define OFF_B2  10656
#define OFF_B3  10688
#define OFF_C1  10692
#define OFF_C2  10724
#define OFF_C3  10788
#define OFF_EW  10916    // 66 used
#define OFF_EB  10984
#define OFF_AB  10988    // buffer: 128 rows x 129 floats
#define SMEM_FLOATS (OFF_AB + 128*129)

__device__ __forceinline__ float sigmoidf(float v) {
    return __fdividef(1.0f, 1.0f + __expf(-v));
}
__device__ __forceinline__ void ffma2(u64& acc, u64 w, u64 v) {
    asm("fma.rn.f32x2 %0, %1, %2, %0;" : "+l"(acc) : "l"(w), "l"(v));
}
__device__ __forceinline__ u64 pack2(float v) {
    u64 r; asm("mov.b64 %0, {%1, %1};" : "=l"(r) : "f"(v)); return r;
}
__device__ __forceinline__ u64 pack2f(float a, float b) {
    u64 r; asm("mov.b64 %0, {%1, %2};" : "=l"(r) : "f"(a), "f"(b)); return r;
}
__device__ __forceinline__ void unpack2(u64 p, float& a, float& b) {
    asm("mov.b64 {%0, %1}, %2;" : "=f"(a), "=f"(b) : "l"(p));
}

// one k-step of a dual (value+tangent) GEMM, NOUT outputs, weights from smem
template<int NOUT>
__device__ __forceinline__ void dual_step(const float* wrow, float hv_s, float tv_s,
                                          u64* aV, u64* aT) {
    u64 hv = pack2(hv_s), tv = pack2(tv_s);
    const ulonglong2* wp = (const ulonglong2*)wrow;
    #pragma unroll
    for (int q = 0; q < NOUT / 4; q++) {
        ulonglong2 wq = wp[q];
        ffma2(aV[2*q],   wq.x, hv);
        ffma2(aV[2*q+1], wq.y, hv);
        ffma2(aT[2*q],   wq.x, tv);
        ffma2(aT[2*q+1], wq.y, tv);
    }
}

template<int NOUT>
__device__ __forceinline__ void init_dual(u64* aV, u64* aT, const float* bias) {
    const u64* bp = (const u64*)bias;
    #pragma unroll
    for (int p = 0; p < NOUT/2; p++) { aV[p] = bp[p]; aT[p] = 0ull; }
}

// sigmoid boundary: value -> row[j], tangent -> row[64+j]
template<int NOUT>
__device__ __forceinline__ void boundary_row(const u64* aV, const u64* aT, float* row) {
    #pragma unroll
    for (int p = 0; p < NOUT/2; p++) {
        float a, b, ta, tb;
        unpack2(aV[p], a, b); unpack2(aT[p], ta, tb);
        float s0 = sigmoidf(a), s1 = sigmoidf(b);
        row[2*p]      = s0;
        row[2*p+1]    = s1;
        row[64+2*p]   = s0 * (1.f - s0) * ta;
        row[64+2*p+1] = s1 * (1.f - s1) * tb;
    }
}

__global__ __launch_bounds__(TPB, 2)
void sindy_fused_kernel(
    const float* __restrict__ x,  const float* __restrict__ dx,
    const float* __restrict__ W1, const float* __restrict__ b1,
    const float* __restrict__ W2, const float* __restrict__ b2,
    const float* __restrict__ W3, const float* __restrict__ b3,
    const float* __restrict__ V1, const float* __restrict__ c1,
    const float* __restrict__ V2, const float* __restrict__ c2,
    const float* __restrict__ V3, const float* __restrict__ c3,
    const float* __restrict__ Ew, const float* __restrict__ Eb,
    float* __restrict__ out, int n)
{
    extern __shared__ float sm[];
    const int tid = threadIdx.x;
    const long long base = (long long)blockIdx.x * NS;

    // ---- W1 window prefetch helpers (2048 elems = 16/thread) ----
    auto prefetch_w1 = [&](int q, float* pw) {
        #pragma unroll
        for (int u = 0; u < 16; u++) {
            int i = tid + u*TPB;
            int j = i >> 5, kl = i & 31;
            pw[u] = W1[j*128 + q*32 + kl];
        }
    };
    auto sts_w1 = [&](const float* pw) {
        #pragma unroll
        for (int u = 0; u < 16; u++) {
            int i = tid + u*TPB;
            int j = i >> 5, kl = i & 31;
            sm[OFF_W1W + kl*68 + j] = pw[u];
        }
    };
    // ---- V3 window prefetch helpers (1024 elems = 8/thread) ----
    auto prefetch_v3 = [&](int w, float* pv) {
        #pragma unroll
        for (int u = 0; u < 8; u++) {
            int i = tid + u*TPB;
            int jl = i >> 6, k = i & 63;
            pv[u] = V3[(w*16 + jl)*64 + k];
        }
    };
    auto sts_v3 = [&](const float* pv) {
        #pragma unroll
        for (int u = 0; u < 8; u++) {
            int i = tid + u*TPB;
            int jl = i >> 6, k = i & 63;
            sm[OFF_V3W + jl*64 + k] = pv[u];
        }
    };

    // ---- stage resident weights + W1 quarter 0 ----
    {
        float pw0[16];
        prefetch_w1(0, pw0);
        sts_w1(pw0);
    }
    for (int i = tid; i < 32*64;  i += TPB) { int j = i >> 6, k = i & 63;  sm[OFF_W2T + k*32 + j] = W2[i]; }
    for (int i = tid; i < 3*32;   i += TPB) { int j = i >> 5, k = i & 31;  sm[OFF_W3T + k*4  + j] = W3[i]; }
    for (int i = tid; i < 32*3;   i += TPB) { int j = i / 3,  k = i % 3;   sm[OFF_V1T + k*32 + j] = V1[i]; }
    for (int i = tid; i < 64*32;  i += TPB) { int j = i >> 5, k = i & 31;  sm[OFF_V2T + k*64 + j] = V2[i]; }
    if (tid < 64)  sm[OFF_B1 + tid] = b1[tid];
    if (tid < 32)  sm[OFF_B2 + tid] = b2[tid];
    if (tid < 4)   sm[OFF_B3 + tid] = (tid < 3) ? b3[tid] : 0.f;
    if (tid < 32)  sm[OFF_C1 + tid] = c1[tid];
    if (tid < 64)  sm[OFF_C2 + tid] = c2[tid];
    if (tid < 128) sm[OFF_C3 + tid] = c3[tid];
    if (tid < 66)  sm[OFF_EW + tid] = Ew[tid];
    if (tid < 3)   sm[OFF_EB + tid] = Eb[tid];

    float* Abuf = sm + OFF_AB;

    long long rem = (long long)n - base;
    const int nv = (rem >= NS) ? NS : (int)rem;
    const bool active = tid < nv;
    float* row = Abuf + tid * 129;

    // stage one 64-column wave of x into row[0:64] and dx into row[64:128]
    auto stage_wave = [&](int w) {
        if (nv == NS) {
            const float4* x4  = (const float4*)x;
            const float4* dx4 = (const float4*)dx;
            for (int i = tid; i < NS * 16; i += TPB) {
                int r = i >> 4, q = i & 15;
                size_t gi = (size_t)(base + r) * 32 + (size_t)w * 16 + q;
                float4 v = x4[gi];
                float* d = &Abuf[r*129 + q*4];
                d[0] = v.x; d[1] = v.y; d[2] = v.z; d[3] = v.w;
                v = dx4[gi];
                d = &Abuf[r*129 + 64 + q*4];
                d[0] = v.x; d[1] = v.y; d[2] = v.z; d[3] = v.w;
            }
        } else {
            for (int i = tid; i < nv * 64; i += TPB) {
                int r = i >> 6, c = i & 63;
                size_t gi = (size_t)(base + r) * 128 + (size_t)w * 64 + c;
                Abuf[r*129 + c]      = x[gi];
                Abuf[r*129 + 64 + c] = dx[gi];
            }
        }
    };

    const size_t n3  = (size_t)n * 3;
    const size_t xbo = (size_t)n * 9;
    const size_t dxo = xbo + (size_t)n * 128;

    // ================= encoder L1: 128 -> 64 (4 k-chunks, prefetched W1 windows) =================
    u64 aV[32], aT[32];
    float pw[16];
    stage_wave(0);
    prefetch_w1(1, pw);                    // LDG q1 overlaps q0 compute
    __syncthreads();                       // wave0 + W1 q0 visible
    if (active) {
        init_dual<64>(aV, aT, &sm[OFF_B1]);
        #pragma unroll 4
        for (int k = 0; k < 32; k++)
            dual_step<64>(&sm[OFF_W1W + k*68], row[k], row[64+k], aV, aT);
    }
    __syncthreads();                       // q0 reads done
    sts_w1(pw);
    prefetch_w1(2, pw);                    // LDG q2 overlaps q1 compute
    __syncthreads();                       // q1 visible
    if (active) {
        #pragma unroll 4
        for (int k = 0; k < 32; k++)
            dual_step<64>(&sm[OFF_W1W + k*68], row[32+k], row[96+k], aV, aT);
    }
    __syncthreads();                       // q1 reads + wave0 reads done
    sts_w1(pw);
    stage_wave(1);
    prefetch_w1(3, pw);                    // LDG q3 overlaps q2 compute
    __syncthreads();                       // q2 + wave1 visible
    if (active) {
        #pragma unroll 4
        for (int k = 0; k < 32; k++)
            dual_step<64>(&sm[OFF_W1W + k*68], row[k], row[64+k], aV, aT);
    }
    __syncthreads();                       // q2 reads done
    sts_w1(pw);
    __syncthreads();                       // q3 visible

    u64 hp[32], tp[32];   // packed h2d/t2d for decoder L3 (filled later)

    if (active) {
        #pragma unroll 4
        for (int k = 0; k < 32; k++)
            dual_step<64>(&sm[OFF_W1W + k*68], row[32+k], row[96+k], aV, aT);
        boundary_row<64>(aV, aT, row);   // h1 -> row[0:64], t1 -> row[64:128]

        // ================= encoder L2: 64 -> 32 =================
        u64 bV[16], bT[16];
        init_dual<32>(bV, bT, &sm[OFF_B2]);
        #pragma unroll 4
        for (int k = 0; k < 64; k++)
            dual_step<32>(&sm[OFF_W2T + k*32], row[k], row[64+k], bV, bT);
        boundary_row<32>(bV, bT, row);   // h2 -> row[0:32], t2 -> row[64:96]

        // ================= encoder L3: 32 -> 3 =================
        float z0 = sm[OFF_B3+0], z1 = sm[OFF_B3+1], z2 = sm[OFF_B3+2];
        float tz0 = 0.f, tz1 = 0.f, tz2 = 0.f;
        #pragma unroll
        for (int k = 0; k < 32; k++) {
            float v = row[k], t = row[64+k];
            float w0 = sm[OFF_W3T + k*4 + 0];
            float w1 = sm[OFF_W3T + k*4 + 1];
            float w2 = sm[OFF_W3T + k*4 + 2];
            z0 += w0*v; tz0 += w0*t;
            z1 += w1*v; tz1 += w1*t;
            z2 += w2*v; tz2 += w2*t;
        }
        size_t sI = (size_t)(base + tid);
        out[     sI*3+0] = z0;  out[     sI*3+1] = z1;  out[     sI*3+2] = z2;   // z
        out[n3 + sI*3+0] = tz0; out[n3 + sI*3+1] = tz1; out[n3 + sI*3+2] = tz2;  // dz

        // ================= SINDy library + dzb =================
        float th[22];
        th[0]=1.f; th[1]=1.f; th[2]=1.f;
        th[3]=z0; th[4]=z1; th[5]=z2;
        th[6]=z0*z0; th[7]=z0*z1; th[8]=z0*z2;
        th[9]=z1*z1; th[10]=z1*z2; th[11]=z2*z2;
        th[12]=th[6]*z0; th[13]=th[6]*z1; th[14]=th[6]*z2;
        th[15]=th[7]*z1; th[16]=th[7]*z2; th[17]=th[8]*z2;
        th[18]=th[9]*z1; th[19]=th[9]*z2; th[20]=th[10]*z2;
        th[21]=th[11]*z2;
        float q0 = sm[OFF_EB+0], q1 = sm[OFF_EB+1], q2 = sm[OFF_EB+2];
        #pragma unroll
        for (int k = 0; k < 22; k++) {
            q0 += sm[OFF_EW +      k] * th[k];
            q1 += sm[OFF_EW + 22 + k] * th[k];
            q2 += sm[OFF_EW + 44 + k] * th[k];
        }
        out[2*n3 + sI*3+0] = q0; out[2*n3 + sI*3+1] = q1; out[2*n3 + sI*3+2] = q2; // dzb

        // ================= decoder L1: 3 -> 32 =================
        u64 dV[16], dT[16];
        init_dual<32>(dV, dT, &sm[OFF_C1]);
        dual_step<32>(&sm[OFF_V1T + 0*32], z0, q0, dV, dT);
        dual_step<32>(&sm[OFF_V1T + 1*32], z1, q1, dV, dT);
        dual_step<32>(&sm[OFF_V1T + 2*32], z2, q2, dV, dT);
        boundary_row<32>(dV, dT, row);   // h1d -> row[0:32], t1d -> row[64:96]

        // ================= decoder L2: 32 -> 64 =================
        u64 eV[32], eT[32];
        init_dual<64>(eV, eT, &sm[OFF_C2]);
        #pragma unroll 4
        for (int k = 0; k < 32; k++)
            dual_step<64>(&sm[OFF_V2T + k*64], row[k], row[64+k], eV, eT);
        // boundary -> packed registers (h2d/t2d pairs for L3)
        #pragma unroll
        for (int p = 0; p < 32; p++) {
            float a, b, ta, tb;
            unpack2(eV[p], a, b); unpack2(eT[p], ta, tb);
            float s0 = sigmoidf(a), s1 = sigmoidf(b);
            hp[p] = pack2f(s0, s1);
            tp[p] = pack2f(s0 * (1.f - s0) * ta, s1 * (1.f - s1) * tb);
        }
    }

    // ================= decoder L3: 64 -> 128, 8 prefetched windows of 16 j =================
    const bool fast = (nv == NS) && ((n & 3) == 0);

    auto dec3_compute = [&](int W) {
        if (active) {
            #pragma unroll 2
            for (int j = 0; j < 16; j++) {
                int jj = W*16 + j;
                int rc = jj & 63;          // slot within row half-buffer
                u64 aV0 = pack2f(sm[OFF_C3 + jj], 0.f);
                u64 aV1 = 0ull, aT0 = 0ull, aT1 = 0ull;
                const ulonglong2* wp = (const ulonglong2*)&sm[OFF_V3W + j*64];
                #pragma unroll
                for (int q = 0; q < 16; q += 2) {
                    ulonglong2 w0 = wp[q], w1 = wp[q+1];
                    ffma2(aV0, w0.x, hp[2*q]);   ffma2(aV0, w0.y, hp[2*q+1]);
                    ffma2(aT0, w0.x, tp[2*q]);   ffma2(aT0, w0.y, tp[2*q+1]);
                    ffma2(aV1, w1.x, hp[2*q+2]); ffma2(aV1, w1.y, hp[2*q+3]);
                    ffma2(aT1, w1.x, tp[2*q+2]); ffma2(aT1, w1.y, tp[2*q+3]);
                }
                float v0,v1,v2,v3,t0,t1,t2,t3;
                unpack2(aV0, v0, v1); unpack2(aV1, v2, v3);
                unpack2(aT0, t0, t1); unpack2(aT1, t2, t3);
                row[rc]      = (v0+v1) + (v2+v3);   // xb col jj
                row[64 + rc] = (t0+t1) + (t2+t3);   // dxb col jj
            }
        }
    };
    auto writeback = [&](int H) {
        if (fast) {
            float4* ox = (float4*)(out + xbo);
            float4* od = (float4*)(out + dxo);
            for (int i = tid; i < NS * 16; i += TPB) {
                int r = i >> 4, q = i & 15;
                size_t gi = (size_t)(base + r) * 32 + (size_t)H * 16 + q;
                const float* ap = &Abuf[r*129 + q*4];
                float4 v; v.x = ap[0]; v.y = ap[1]; v.z = ap[2]; v.w = ap[3];
                ox[gi] = v;
                const float* bp = &Abuf[r*129 + 64 + q*4];
                v.x = bp[0]; v.y = bp[1]; v.z = bp[2]; v.w = bp[3];
                od[gi] = v;
            }
        } else {
            for (int i = tid; i < nv * 64; i += TPB) {
                int r = i >> 6, c = i & 63;
                size_t gi = (size_t)(base + r) * 128 + (size_t)H * 64 + c;
                out[xbo + gi] = Abuf[r*129 + c];
                out[dxo + gi] = Abuf[r*129 + 64 + c];
            }
        }
    };

    float pv[8];
    prefetch_v3(0, pv);
    #pragma unroll 1
    for (int W = 0; W < 8; W++) {
        sts_v3(pv);
        if (W < 7) prefetch_v3(W + 1, pv);   // LDG next window under this compute
        __syncthreads();          // window staged
        dec3_compute(W);
        __syncthreads();          // computes done before restage / writeback
        if (W == 3) {
            writeback(0);         // cols 0..63 complete
            __syncthreads();      // writeback done before rows overwritten
        }
    }
    writeback(1);                 // cols 64..127 (post final sync above)
}

extern "C" void kernel_launch(void* const* d_in, const int* in_sizes, int n_in,
                              void* d_out, int out_size) {
    (void)n_in; (void)out_size;
    const float* x  = (const float*)d_in[0];
    const float* dx = (const float*)d_in[1];
    const float* W1 = (const float*)d_in[2];
    const float* b1 = (const float*)d_in[3];
    const float* W2 = (const float*)d_in[4];
    const float* b2 = (const float*)d_in[5];
    const float* W3 = (const float*)d_in[6];
    const float* b3 = (const float*)d_in[7];
    const float* V1 = (const float*)d_in[8];
    const float* c1 = (const float*)d_in[9];
    const float* V2 = (const float*)d_in[10];
    const float* c2 = (const float*)d_in[11];
    const float* V3 = (const float*)d_in[12];
    const float* c3 = (const float*)d_in[13];
    const float* Ew = (const float*)d_in[14];
    const float* Eb = (const float*)d_in[15];
    float* out = (float*)d_out;

    const int n = in_sizes[0] / 128;
    const size_t smem = SMEM_FLOATS * sizeof(float);
    cudaFuncSetAttribute(sindy_fused_kernel,
                         cudaFuncAttributeMaxDynamicSharedMemorySize, (int)smem);
    const int grid = (n + NS - 1) / NS;
    sindy_fused_kernel<<<grid, TPB, smem>>>(x, dx, W1, b1, W2, b2, W3, b3,
                                            V1, c1, V2, c2, V3, c3, Ew, Eb,
                                            out, n);
}